// round 16
// baseline (speedup 1.0000x reference)
#include <cuda_runtime.h>

// Problem constants
#define D_TOT   1296
#define K_PTS   64
#define R_RANK  16
#define F_SUB   408
#define DT      (200.0f / 64.0f)
#define D_PER_BLOCK 3
#define GRID_A  (D_TOT / D_PER_BLOCK)      // 432  (<= 444 co-resident capacity)
#define OUT_SCALE (DT / (float)D_TOT)

#define OUT_INTERLEAVED 0
#define OUT_REAL_ONLY   1

// Per-block partials, fully overwritten every replay.
// Layout per block: [tid*32 + 0..15] = T_re, [tid*32 + 16..31] = T_im,
//                   [8192 + tid] = M1_re, [8448 + tid] = M1_im.
#define PART_LEN 8704
#define RED_CHUNKS 12
#define RED_BPC (GRID_A / RED_CHUNKS)      // 36
__device__ __align__(16) float g_part[GRID_A][PART_LEN];
__device__ __align__(16) float g_acc[PART_LEN];

// ---- device-wide barrier (sense-reversing via monotonic generation).
// Self-cleaning across graph replays: g_cnt returns to 0 at every release,
// g_gen only ever increments (waiters compare against their snapshot).
__device__ unsigned g_cnt;            // zero-initialized
__device__ volatile unsigned g_gen;   // zero-initialized

__device__ __forceinline__ void grid_sync() {
    __syncthreads();
    if (threadIdx.x == 0) {
        __threadfence();                       // release block's writes
        unsigned my_gen = g_gen;
        unsigned old = atomicAdd(&g_cnt, 1);
        if (old == GRID_A - 1) {
            g_cnt = 0;
            __threadfence();
            g_gen = my_gen + 1;                // release the barrier
        } else {
            while (g_gen == my_gen) { }        // spin on volatile
        }
        __threadfence();                       // acquire others' writes
    }
    __syncthreads();
}

// ---- single fused kernel: accum -> barrier -> reduce -> barrier -> csi ----
__global__ __launch_bounds__(256, 3) void fused_kernel(
    const float* __restrict__ att_re, const float* __restrict__ att_im,
    const float* __restrict__ rad_re, const float* __restrict__ rad_im,
    const float* __restrict__ f_re,  const float* __restrict__ f_im,
    float* __restrict__ out, int mode)
{
    __shared__ __align__(16) float2 s_a[K_PTS * R_RANK];   // att interleaved
    __shared__ __align__(16) float2 s_b[K_PTS * R_RANK];   // rad interleaved
    __shared__ __align__(16) float  s_cre[K_PTS * R_RANK];
    __shared__ __align__(16) float  s_cim[K_PTS * R_RANK];
    __shared__ float s_chunk[2][4][16];                    // scan partials

    const int tid = threadIdx.x;
    const int bid = blockIdx.x;
    const int i = tid >> 4;
    const int j = tid & 15;

    // ===================== Phase 1: accumulate partials =====================
    // Blocks 0..33 also zero g_acc (untouched by phase 1 otherwise).
    if (bid < PART_LEN / 256)
        g_acc[bid * 256 + tid] = 0.0f;

    float tre[16], tim[16];
#pragma unroll
    for (int l = 0; l < 16; ++l) { tre[l] = 0.0f; tim[l] = 0.0f; }
    float m1r = 0.0f, m1i = 0.0f;

    for (int dd = 0; dd < D_PER_BLOCK; ++dd) {
        const int d = bid * D_PER_BLOCK + dd;
        const long base4 = (long)d * (K_PTS * R_RANK / 4);
        {
            float4 ar4 = reinterpret_cast<const float4*>(att_re)[base4 + tid];
            float4 ai4 = reinterpret_cast<const float4*>(att_im)[base4 + tid];
            float4 br4 = reinterpret_cast<const float4*>(rad_re)[base4 + tid];
            float4 bi4 = reinterpret_cast<const float4*>(rad_im)[base4 + tid];
            const int o = tid * 4;
            s_a[o + 0] = make_float2(ar4.x, ai4.x);
            s_a[o + 1] = make_float2(ar4.y, ai4.y);
            s_a[o + 2] = make_float2(ar4.z, ai4.z);
            s_a[o + 3] = make_float2(ar4.w, ai4.w);
            s_b[o + 0] = make_float2(br4.x, bi4.x);
            s_b[o + 1] = make_float2(br4.y, bi4.y);
            s_b[o + 2] = make_float2(br4.z, bi4.z);
            s_b[o + 3] = make_float2(br4.w, bi4.w);
        }
        __syncthreads();

        // Two-phase parallel cumsum: c[k][l] = DT * cumsum_k(att[k][l]).
        const int l_s = tid & 15;
        const int plane = (tid >> 4) & 1;
        const int q = tid >> 5;
        if (tid < 128) {
            float sum = 0.0f;
#pragma unroll
            for (int kk = 0; kk < 16; ++kk) {
                float2 v = s_a[(q * 16 + kk) * 16 + l_s];
                sum += plane ? v.y : v.x;
            }
            s_chunk[plane][q][l_s] = sum;
        }
        __syncthreads();
        if (tid < 128) {
            float run = 0.0f;
#pragma unroll
            for (int qq = 0; qq < 3; ++qq)
                if (qq < q) run += s_chunk[plane][qq][l_s];
            float* dst = plane ? s_cim : s_cre;
#pragma unroll
            for (int kk = 0; kk < 16; ++kk) {
                float2 v = s_a[(q * 16 + kk) * 16 + l_s];
                run += plane ? v.y : v.x;
                dst[(q * 16 + kk) * 16 + l_s] = DT * run;
            }
        }
        __syncthreads();

        // k = 0 peel: first order (M1) only
        {
            float2 a = s_a[j];
            float2 b = s_b[i];
            m1r += b.x * a.x - b.y * a.y;
            m1i -= b.x * a.y + b.y * a.x;
        }

#pragma unroll 2
        for (int k = 1; k < K_PTS; ++k) {
            float2 a = s_a[k * 16 + j];
            float2 b = s_b[k * 16 + i];
            // w = conj(rad_i) * conj(att_j)
            float wr = fmaf(b.x, a.x, -b.y * a.y);
            float wi = -fmaf(b.x, a.y, b.y * a.x);
            m1r += wr;
            m1i += wi;

            const float4* cr4 = reinterpret_cast<const float4*>(s_cre + k * 16);
            const float4* ci4 = reinterpret_cast<const float4*>(s_cim + k * 16);
#pragma unroll
            for (int p = 0; p < 4; ++p) {
                float4 cr = cr4[p];
                float4 ci = ci4[p];
                tre[4*p+0] = fmaf(wr, cr.x, fmaf(-wi, ci.x, tre[4*p+0]));
                tim[4*p+0] = fmaf(wr, ci.x, fmaf( wi, cr.x, tim[4*p+0]));
                tre[4*p+1] = fmaf(wr, cr.y, fmaf(-wi, ci.y, tre[4*p+1]));
                tim[4*p+1] = fmaf(wr, ci.y, fmaf( wi, cr.y, tim[4*p+1]));
                tre[4*p+2] = fmaf(wr, cr.z, fmaf(-wi, ci.z, tre[4*p+2]));
                tim[4*p+2] = fmaf(wr, ci.z, fmaf( wi, cr.z, tim[4*p+2]));
                tre[4*p+3] = fmaf(wr, cr.w, fmaf(-wi, ci.w, tre[4*p+3]));
                tim[4*p+3] = fmaf(wr, ci.w, fmaf( wi, cr.w, tim[4*p+3]));
            }
        }
        __syncthreads();
    }

    // Write per-block partials (coalesced float4 stores)
    {
        float* pT = g_part[bid] + tid * 32;
#pragma unroll
        for (int p = 0; p < 4; ++p)
            reinterpret_cast<float4*>(pT)[p] =
                make_float4(tre[4*p], tre[4*p+1], tre[4*p+2], tre[4*p+3]);
#pragma unroll
        for (int p = 0; p < 4; ++p)
            reinterpret_cast<float4*>(pT + 16)[p] =
                make_float4(tim[4*p], tim[4*p+1], tim[4*p+2], tim[4*p+3]);
        g_part[bid][8192 + tid] = m1r;
        g_part[bid][8448 + tid] = m1i;
    }

    grid_sync();

    // ===================== Phase 2: fold partials into g_acc ================
    // 408 blocks: block = chunk*34 + vgroup; sums 36 partials, REDG to g_acc.
    if (bid < 34 * RED_CHUNKS) {
        const int c  = bid / 34;
        const int vg = bid % 34;
        const int v  = vg * 256 + tid;
        const int b0 = c * RED_BPC;
        float s0 = 0.f, s1 = 0.f, s2 = 0.f, s3 = 0.f, s4 = 0.f, s5 = 0.f;
#pragma unroll 1
        for (int n = 0; n < RED_BPC; n += 6) {      // 36 = 6*6
            s0 += g_part[b0 + n + 0][v];
            s1 += g_part[b0 + n + 1][v];
            s2 += g_part[b0 + n + 2][v];
            s3 += g_part[b0 + n + 3][v];
            s4 += g_part[b0 + n + 4][v];
            s5 += g_part[b0 + n + 5][v];
        }
        atomicAdd(&g_acc[v], ((s0 + s1) + (s2 + s3)) + (s4 + s5));
    }

    grid_sync();

    // ===================== Phase 3: csi contraction (blocks 0..50) ==========
    if (bid < 51) {
        __shared__ float2 s_f[8][16];   // per-warp f vector (re, im)
        const int lane = tid & 31;
        const int w    = tid >> 5;
        const int f = bid * 8 + w;

        if (lane < 16)
            s_f[w][lane] = make_float2(f_re[f * R_RANK + lane],
                                       f_im[f * R_RANK + lane]);
        __syncwarp();

        float accr = 0.0f, acci = 0.0f;
#pragma unroll
        for (int p = 0; p < 8; ++p) {
            const int ij = lane + 32 * p;
            const int ii = ij >> 4;
            const int jj = ij & 15;

            float sr = g_acc[8192 + ij];
            float si = g_acc[8448 + ij];
            const float4* tr4 = reinterpret_cast<const float4*>(g_acc + ij * 32);
            const float4* ti4 = reinterpret_cast<const float4*>(g_acc + ij * 32 + 16);
#pragma unroll
            for (int q = 0; q < 4; ++q) {
                float4 tr = tr4[q];
                float4 ti = ti4[q];
#pragma unroll
                for (int s = 0; s < 4; ++s) {
                    float trv = (s == 0) ? tr.x : (s == 1) ? tr.y : (s == 2) ? tr.z : tr.w;
                    float tiv = (s == 0) ? ti.x : (s == 1) ? ti.y : (s == 2) ? ti.z : ti.w;
                    float2 fl = s_f[w][4 * q + s];
                    sr = fmaf(trv, fl.x, fmaf(-tiv, fl.y, sr));
                    si = fmaf(trv, fl.y, fmaf( tiv, fl.x, si));
                }
            }
            float2 fiv = s_f[w][ii];
            float2 fjv = s_f[w][jj];
            float pr  = fiv.x * fjv.x - fiv.y * fjv.y;
            float pi_ = fiv.x * fjv.y + fiv.y * fjv.x;
            accr += pr * sr - pi_ * si;
            acci += pr * si + pi_ * sr;
        }

#pragma unroll
        for (int off = 16; off > 0; off >>= 1) {
            accr += __shfl_down_sync(0xFFFFFFFFu, accr, off);
            acci += __shfl_down_sync(0xFFFFFFFFu, acci, off);
        }
        if (lane == 0) {
            float re = accr * OUT_SCALE;
            float im = acci * OUT_SCALE;
            if (mode == OUT_REAL_ONLY) {
                out[f] = re;                   // float32(csi) == Re(csi)
            } else {
                out[2 * f]     = re;
                out[2 * f + 1] = im;
            }
        }
    }
}

extern "C" void kernel_launch(void* const* d_in, const int* in_sizes, int n_in,
                              void* d_out, int out_size)
{
    // Established (round 6 PASS): out_size == 408 -> real-part-only output,
    // inputs in dict/signature order.
    const float *att_re, *att_im, *rad_re, *rad_im, *f_re, *f_im;
    int mode;

    if (out_size == F_SUB) {
        att_re = (const float*)d_in[0];
        att_im = (const float*)d_in[1];
        rad_re = (const float*)d_in[2];
        rad_im = (const float*)d_in[3];
        mode = OUT_REAL_ONLY;
    } else {
        rad_re = (const float*)d_in[0];
        rad_im = (const float*)d_in[1];
        att_re = (const float*)d_in[2];
        att_im = (const float*)d_in[3];
        mode = OUT_INTERLEAVED;
    }
    f_re = (const float*)d_in[4];
    f_im = (const float*)d_in[5];

    float* out = (float*)d_out;

    fused_kernel<<<GRID_A, 256>>>(att_re, att_im, rad_re, rad_im,
                                  f_re, f_im, out, mode);
}

// round 17
// speedup vs baseline: 1.0439x; 1.0439x over previous
#include <cuda_runtime.h>

// Problem constants
#define D_TOT   1296
#define K_PTS   64
#define R_RANK  16
#define F_SUB   408
#define DT      (200.0f / 64.0f)
#define D_PER_BLOCK 3
#define GRID_A  (D_TOT / D_PER_BLOCK)      // 432
#define OUT_SCALE (DT / (float)D_TOT)

#define OUT_INTERLEAVED 0
#define OUT_REAL_ONLY   1

#define PART_LEN 8704
#define RED_CHUNKS 12
#define RED_BPC (GRID_A / RED_CHUNKS)      // 36
__device__ __align__(16) float g_part[GRID_A][PART_LEN];
__device__ __align__(16) float g_part2[RED_CHUNKS][PART_LEN];
__device__ __align__(16) float g_acc[PART_LEN];

// ---- packed f32x2 helpers ----
__device__ __forceinline__ unsigned long long fma2(unsigned long long a,
                                                   unsigned long long b,
                                                   unsigned long long c) {
    unsigned long long d;
    asm("fma.rn.f32x2 %0, %1, %2, %3;" : "=l"(d) : "l"(a), "l"(b), "l"(c));
    return d;
}
__device__ __forceinline__ unsigned long long pack2(float lo, float hi) {
    unsigned long long r;
    asm("mov.b64 %0, {%1, %2};" : "=l"(r) : "f"(lo), "f"(hi));
    return r;
}
__device__ __forceinline__ void unpack2(unsigned long long v, float& lo, float& hi) {
    asm("mov.b64 {%0, %1}, %2;" : "=f"(lo), "=f"(hi) : "l"(v));
}

// ---- kernel A: accumulate T[i,j,l] and M1[i,j] over (d,k) ----
// Structure identical to the proven 84.4-us version; ONLY the T update is
// switched to packed fma.rn.f32x2 (accumulators stay packed across k).
__global__ __launch_bounds__(256) void accum_kernel(
    const float* __restrict__ att_re, const float* __restrict__ att_im,
    const float* __restrict__ rad_re, const float* __restrict__ rad_im)
{
    __shared__ __align__(16) float2 s_a[K_PTS * R_RANK];   // att interleaved
    __shared__ __align__(16) float2 s_b[K_PTS * R_RANK];   // rad interleaved
    __shared__ __align__(16) float  s_cre[K_PTS * R_RANK];
    __shared__ __align__(16) float  s_cim[K_PTS * R_RANK];
    __shared__ float s_chunk[2][4][16];                    // scan partials

    const int tid = threadIdx.x;
    const int i = tid >> 4;
    const int j = tid & 15;

    unsigned long long tre[8], tim[8];
#pragma unroll
    for (int p = 0; p < 8; ++p) { tre[p] = 0ull; tim[p] = 0ull; }
    float m1r = 0.0f, m1i = 0.0f;

    for (int dd = 0; dd < D_PER_BLOCK; ++dd) {
        const int d = blockIdx.x * D_PER_BLOCK + dd;
        const long base4 = (long)d * (K_PTS * R_RANK / 4);
        {
            float4 ar4 = reinterpret_cast<const float4*>(att_re)[base4 + tid];
            float4 ai4 = reinterpret_cast<const float4*>(att_im)[base4 + tid];
            float4 br4 = reinterpret_cast<const float4*>(rad_re)[base4 + tid];
            float4 bi4 = reinterpret_cast<const float4*>(rad_im)[base4 + tid];
            const int o = tid * 4;
            s_a[o + 0] = make_float2(ar4.x, ai4.x);
            s_a[o + 1] = make_float2(ar4.y, ai4.y);
            s_a[o + 2] = make_float2(ar4.z, ai4.z);
            s_a[o + 3] = make_float2(ar4.w, ai4.w);
            s_b[o + 0] = make_float2(br4.x, bi4.x);
            s_b[o + 1] = make_float2(br4.y, bi4.y);
            s_b[o + 2] = make_float2(br4.z, bi4.z);
            s_b[o + 3] = make_float2(br4.w, bi4.w);
        }
        __syncthreads();

        // Two-phase parallel cumsum: c[k][l] = DT * cumsum_k(att[k][l]).
        const int l_s = tid & 15;
        const int plane = (tid >> 4) & 1;
        const int q = tid >> 5;
        if (tid < 128) {
            float sum = 0.0f;
#pragma unroll
            for (int kk = 0; kk < 16; ++kk) {
                float2 v = s_a[(q * 16 + kk) * 16 + l_s];
                sum += plane ? v.y : v.x;
            }
            s_chunk[plane][q][l_s] = sum;
        }
        __syncthreads();
        if (tid < 128) {
            float run = 0.0f;
#pragma unroll
            for (int qq = 0; qq < 3; ++qq)
                if (qq < q) run += s_chunk[plane][qq][l_s];
            float* dst = plane ? s_cim : s_cre;
#pragma unroll
            for (int kk = 0; kk < 16; ++kk) {
                float2 v = s_a[(q * 16 + kk) * 16 + l_s];
                run += plane ? v.y : v.x;
                dst[(q * 16 + kk) * 16 + l_s] = DT * run;
            }
        }
        __syncthreads();

        // k = 0 peel: first order (M1) only
        {
            float2 a = s_a[j];
            float2 b = s_b[i];
            m1r += b.x * a.x - b.y * a.y;
            m1i -= b.x * a.y + b.y * a.x;
        }

#pragma unroll 2
        for (int k = 1; k < K_PTS; ++k) {
            float2 a = s_a[k * 16 + j];
            float2 b = s_b[k * 16 + i];
            // w = conj(rad_i) * conj(att_j)
            float wr = fmaf(b.x, a.x, -b.y * a.y);
            float wi = -fmaf(b.x, a.y, b.y * a.x);
            m1r += wr;
            m1i += wi;

            unsigned long long wr2 = pack2(wr, wr);
            unsigned long long wi2 = pack2(wi, wi);
            unsigned long long nw2 = pack2(-wi, -wi);

            const ulonglong2* cre2 =
                reinterpret_cast<const ulonglong2*>(s_cre + k * 16);
            const ulonglong2* cim2 =
                reinterpret_cast<const ulonglong2*>(s_cim + k * 16);
#pragma unroll
            for (int p = 0; p < 4; ++p) {
                ulonglong2 cr = cre2[p];
                ulonglong2 ci = cim2[p];
                tre[2*p]   = fma2(wr2, cr.x, tre[2*p]);
                tre[2*p]   = fma2(nw2, ci.x, tre[2*p]);
                tim[2*p]   = fma2(wr2, ci.x, tim[2*p]);
                tim[2*p]   = fma2(wi2, cr.x, tim[2*p]);
                tre[2*p+1] = fma2(wr2, cr.y, tre[2*p+1]);
                tre[2*p+1] = fma2(nw2, ci.y, tre[2*p+1]);
                tim[2*p+1] = fma2(wr2, ci.y, tim[2*p+1]);
                tim[2*p+1] = fma2(wi2, cr.y, tim[2*p+1]);
            }
        }
        __syncthreads();   // before next dd overwrites shared
    }

    // Write per-block partials (coalesced float4 stores)
    float* pT = g_part[blockIdx.x] + tid * 32;
#pragma unroll
    for (int p = 0; p < 8; ++p) {
        float lo, hi;
        unpack2(tre[p], lo, hi);
        pT[2*p]     = lo;
        pT[2*p + 1] = hi;
        unpack2(tim[p], lo, hi);
        pT[16 + 2*p]     = lo;
        pT[16 + 2*p + 1] = hi;
    }
    g_part[blockIdx.x][8192 + tid] = m1r;
    g_part[blockIdx.x][8448 + tid] = m1i;
}

// ---- reduce stage 1: fold 36 partials per chunk (grid 34 x 12) ----
__global__ __launch_bounds__(256) void reduce1_kernel() {
    const int v = blockIdx.x * 256 + threadIdx.x;   // 34*256 = 8704
    const int c = blockIdx.y;
    const int b0 = c * RED_BPC;
    float s0 = 0.f, s1 = 0.f, s2 = 0.f, s3 = 0.f, s4 = 0.f, s5 = 0.f;
#pragma unroll 1
    for (int n = 0; n < RED_BPC; n += 6) {          // 36 = 6*6
        s0 += g_part[b0 + n + 0][v];
        s1 += g_part[b0 + n + 1][v];
        s2 += g_part[b0 + n + 2][v];
        s3 += g_part[b0 + n + 3][v];
        s4 += g_part[b0 + n + 4][v];
        s5 += g_part[b0 + n + 5][v];
    }
    g_part2[c][v] = ((s0 + s1) + (s2 + s3)) + (s4 + s5);
}

// ---- reduce stage 2: fold 12 chunk sums (grid 34) ----
__global__ __launch_bounds__(256) void reduce2_kernel() {
    const int v = blockIdx.x * 256 + threadIdx.x;
    float s = 0.0f;
#pragma unroll
    for (int c = 0; c < RED_CHUNKS; ++c) s += g_part2[c][v];
    g_acc[v] = s;
}

// ---- kernel B: warp-per-f, f-vector in shared (round-14 proven) ----
__global__ __launch_bounds__(256) void csi_kernel(
    const float* __restrict__ f_re, const float* __restrict__ f_im,
    float* __restrict__ out, int mode)
{
    __shared__ float2 s_f[8][16];   // per-warp f vector (re, im)

    const int tid  = threadIdx.x;
    const int lane = tid & 31;
    const int w    = tid >> 5;
    const int f = blockIdx.x * 8 + w;

    if (lane < 16)
        s_f[w][lane] = make_float2(f_re[f * R_RANK + lane],
                                   f_im[f * R_RANK + lane]);
    __syncwarp();

    float accr = 0.0f, acci = 0.0f;
#pragma unroll
    for (int p = 0; p < 8; ++p) {
        const int ij = lane + 32 * p;
        const int i = ij >> 4;
        const int j = ij & 15;

        float sr = g_acc[8192 + ij];
        float si = g_acc[8448 + ij];
        const float4* tr4 = reinterpret_cast<const float4*>(g_acc + ij * 32);
        const float4* ti4 = reinterpret_cast<const float4*>(g_acc + ij * 32 + 16);
#pragma unroll
        for (int q = 0; q < 4; ++q) {
            float4 tr = tr4[q];
            float4 ti = ti4[q];
#pragma unroll
            for (int s = 0; s < 4; ++s) {
                float trv = (s == 0) ? tr.x : (s == 1) ? tr.y : (s == 2) ? tr.z : tr.w;
                float tiv = (s == 0) ? ti.x : (s == 1) ? ti.y : (s == 2) ? ti.z : ti.w;
                float2 fl = s_f[w][4 * q + s];   // LDS.64 broadcast
                sr = fmaf(trv, fl.x, fmaf(-tiv, fl.y, sr));
                si = fmaf(trv, fl.y, fmaf( tiv, fl.x, si));
            }
        }
        float2 fiv = s_f[w][i];
        float2 fjv = s_f[w][j];
        float pr  = fiv.x * fjv.x - fiv.y * fjv.y;
        float pi_ = fiv.x * fjv.y + fiv.y * fjv.x;
        accr += pr * sr - pi_ * si;
        acci += pr * si + pi_ * sr;
    }

#pragma unroll
    for (int off = 16; off > 0; off >>= 1) {
        accr += __shfl_down_sync(0xFFFFFFFFu, accr, off);
        acci += __shfl_down_sync(0xFFFFFFFFu, acci, off);
    }
    if (lane == 0) {
        float re = accr * OUT_SCALE;
        float im = acci * OUT_SCALE;
        if (mode == OUT_REAL_ONLY) {
            out[f] = re;                       // float32(csi) == Re(csi)
        } else {
            out[2 * f]     = re;
            out[2 * f + 1] = im;
        }
    }
}

extern "C" void kernel_launch(void* const* d_in, const int* in_sizes, int n_in,
                              void* d_out, int out_size)
{
    // Established (round 6 PASS): out_size == 408 -> real-part-only output,
    // inputs in dict/signature order.
    const float *att_re, *att_im, *rad_re, *rad_im, *f_re, *f_im;
    int mode;

    if (out_size == F_SUB) {
        att_re = (const float*)d_in[0];
        att_im = (const float*)d_in[1];
        rad_re = (const float*)d_in[2];
        rad_im = (const float*)d_in[3];
        mode = OUT_REAL_ONLY;
    } else {
        rad_re = (const float*)d_in[0];
        rad_im = (const float*)d_in[1];
        att_re = (const float*)d_in[2];
        att_im = (const float*)d_in[3];
        mode = OUT_INTERLEAVED;
    }
    f_re = (const float*)d_in[4];
    f_im = (const float*)d_in[5];

    float* out = (float*)d_out;

    accum_kernel<<<GRID_A, 256>>>(att_re, att_im, rad_re, rad_im);
    reduce1_kernel<<<dim3(34, RED_CHUNKS), 256>>>();
    reduce2_kernel<<<34, 256>>>();
    csi_kernel<<<51, 256>>>(f_re, f_im, out, mode);
}